// round 16
// baseline (speedup 1.0000x reference)
#include <cuda_runtime.h>
#include <cstdint>

#define DIMV 128
#define NA 16
#define NMOL 64
#define NTOT 1024
#define EPSV 1e-12f

typedef unsigned long long ull;

// cross-block scratch (allocation-free: __device__ globals)
__device__ float g_Wm[NMOL * DIMV];
__device__ int   g_ctr;           // monotonic grid-barrier ticket counter

// dynamic smem layout (floats)
#define OFF_E    0                    // E_bond tile: 256 x 128 = 32768
#define OFF_P    (OFF_E + 32768)      // GEMM partials 4x16x128 = 8192; phase-B scratch
#define OFF_M    (OFF_P + 8192)       // mps0 -> mps : 16x128 = 2048
#define OFF_C    (OFF_M + 2048)       // contri 16x128; later bilArr/mmArr
#define OFF_RED  (OFF_C + 2048)       // 2 x (8x128) partials = 2048
#define OFF_ADJ  (OFF_RED + 2048)     // 16x16 adjacency block
#define OFF_NORM (OFF_ADJ + 256)      // 16 inverse norms (padded)
#define OFF_IDX  (OFF_NORM + 32)      // 16 fp indices (padded)
#define OFF_IDXB (OFF_IDX + 32)       // 256 bond indices
#define SMEM_FLOATS (OFF_IDXB + 256)

extern __shared__ float smem[];

__device__ __forceinline__ void cp_async16(unsigned int saddr, const void* gptr) {
    asm volatile("cp.async.cg.shared.global [%0], [%1], 16;\n"
                 :: "r"(saddr), "l"(gptr));
}
#define LDS_V2U64(d0, d1, addr) \
    asm volatile("ld.shared.v2.u64 {%0,%1}, [%2];" : "=l"(d0), "=l"(d1) : "r"(addr))
#define LDS_U64(d, addr) \
    asm volatile("ld.shared.b64 %0, [%1];" : "=l"(d) : "r"(addr))
#define STS_U64(addr, v) \
    asm volatile("st.shared.b64 [%0], %1;" :: "r"(addr), "l"(v) : "memory")
#define FMA2(acc, a, b) \
    asm("fma.rn.f32x2 %0, %1, %2, %0;" : "+l"(acc) : "l"(a), "l"(b))
#define ADD2(acc, a) \
    asm("add.rn.f32x2 %0, %1, %0;" : "+l"(acc) : "l"(a))
#define PACK2(d, lo, hi) \
    asm("mov.b64 %0, {%1, %2};" : "=l"(d) : "f"(lo), "f"(hi))
#define UNPACK2(lo, hi, d) \
    asm("mov.b64 {%0, %1}, %2;" : "=f"(lo), "=f"(hi) : "l"(d))

__global__ __launch_bounds__(512, 1) void k_fused(
    const int* __restrict__ fp, const float* __restrict__ adj,
    const int* __restrict__ bidx, const float* __restrict__ E_fp,
    const float* __restrict__ E_bond, const float* __restrict__ W_fp,
    const float* __restrict__ b_fp,
    const float* __restrict__ W0, const float* __restrict__ b0,
    const float* __restrict__ W1, const float* __restrict__ b1,
    const float* __restrict__ Wp, const float* __restrict__ bp,
    float* __restrict__ out)
{
    float* sE   = smem + OFF_E;
    float* sP   = smem + OFF_P;
    float* sM   = smem + OFF_M;
    float* sC   = smem + OFF_C;
    float* sRedB = smem + OFF_RED;          // bil partials 8x128
    float* sRedW = smem + OFF_RED + 1024;   // wm partials 8x128
    float* sAdj = smem + OFF_ADJ;
    float* sNorm = smem + OFF_NORM;
    int* sIdx  = (int*)(smem + OFF_IDX);
    int* sIdxB = (int*)(smem + OFF_IDXB);
    // phase-B scratch aliases sP (dead after stage 2) and sC (dead after stage 3)
    float* sPart  = sP;                 // 4x128
    float* sx     = sP + 512;           // 128
    float* sy     = sP + 640;           // 128
    float* sr     = sP + 768;           // 4
    float* bilArr = sC;                 // 128
    float* mmArr  = sC + 128;           // 128

    const int tid = threadIdx.x;
    const int m = blockIdx.x;
    const int base = m * NA;
    const int c = tid & 127;
    const int g = tid >> 7;      // 0..3
    const int r0 = 4 * g;
    const unsigned sM_b = (unsigned)__cvta_generic_to_shared(sM);
    const unsigned sE_b = (unsigned)__cvta_generic_to_shared(sE);

    // ---- stage 0: indices + adjacency + scalars + packed W_fp slice ----
    if (tid < NA) sIdx[tid] = fp[base + tid];
    if (tid < NA * NA) {
        int a = tid >> 4, b = tid & 15;
        sIdxB[tid] = bidx[(base + a) * NTOT + base + b];
        sAdj[tid] = adj[(base + a) * NTOT + base + b];
    }
    float bv  = b_fp[c];
    float e0c = E_bond[c];
    ull wp[16];
    #pragma unroll
    for (int j = 0; j < 16; j++) {
        float wlo = W_fp[(g * 32 + 2 * j) * DIMV + c];
        float whi = W_fp[(g * 32 + 2 * j + 1) * DIMV + c];
        PACK2(wp[j], wlo, whi);
    }
    __syncthreads();

    // ---- stage 1: async E_bond gather (hidden) + E_fp gather ----
    {
        const float4* Eb4 = (const float4*)E_bond;
        unsigned int sE_base = sE_b;
        #pragma unroll
        for (int i = tid; i < NA * NA * (DIMV / 4); i += 512) {
            int row = i >> 5, cc = i & 31;
            cp_async16(sE_base + i * 16, &Eb4[sIdxB[row] * (DIMV / 4) + cc]);
        }
        asm volatile("cp.async.commit_group;\n");
    }
    {
        const float4* Ef4 = (const float4*)E_fp;
        float4* sM4 = (float4*)sM;
        int r = tid >> 5, cc = tid & 31;
        sM4[tid] = Ef4[sIdx[r] * (DIMV / 4) + cc];
    }
    __syncthreads();

    // ---- stage 2: contri GEMM partials, k-split 4 ways, f32x2 k-pairs ----
    {
        #pragma unroll
        for (int r = 0; r < NA; r++) {
            unsigned rowaddr = sM_b + (unsigned)(r * DIMV + g * 32) * 4u;
            ull accA = 0ULL, accB = 0ULL;
            #pragma unroll
            for (int q = 0; q < 8; q++) {
                ull d0, d1;
                LDS_V2U64(d0, d1, rowaddr + q * 16);
                FMA2(accA, d0, wp[2 * q]);
                FMA2(accB, d1, wp[2 * q + 1]);
            }
            float a0, a1, a2, a3;
            UNPACK2(a0, a1, accA);
            UNPACK2(a2, a3, accB);
            sP[(g * NA + r) * DIMV + c] = (a0 + a1) + (a2 + a3);
        }
    }
    __syncthreads();

    // reduce partials -> contri = relu(. + b)
    {
        #pragma unroll
        for (int j = 0; j < 4; j++) {
            int r = r0 + j;
            float v = bv + sP[r * DIMV + c] + sP[(NA + r) * DIMV + c]
                    + sP[(2 * NA + r) * DIMV + c] + sP[(3 * NA + r) * DIMV + c];
            sC[r * DIMV + c] = fmaxf(v, 0.f);
        }
    }
    __syncthreads();

    // ---- stage 3: mps = mps0 + adj_block @ contri (in place on sM) ----
    {
        #pragma unroll
        for (int j = 0; j < 4; j++) {
            int r = r0 + j;
            float v = sM[r * DIMV + c];
            #pragma unroll
            for (int b = 0; b < NA; b++)
                v += sAdj[r * NA + b] * sC[b * DIMV + c];
            sM[r * DIMV + c] = v;
        }
    }
    __syncthreads();

    // ---- stage 4: per-row L2 norms (16 warps, warp w -> row w) ----
    {
        int w = tid >> 5, l = tid & 31;
        float v0 = sM[w * DIMV + l], v1 = sM[w * DIMV + l + 32];
        float v2 = sM[w * DIMV + l + 64], v3 = sM[w * DIMV + l + 96];
        float s = v0 * v0 + v1 * v1 + v2 * v2 + v3 * v3;
        #pragma unroll
        for (int o = 16; o > 0; o >>= 1) s += __shfl_xor_sync(0xffffffffu, s, o);
        if (l == 0) sNorm[w] = 1.0f / fmaxf(sqrtf(s), EPSV);
    }
    __syncthreads();
    {
        #pragma unroll
        for (int j = 0; j < 4; j++)
            sM[(r0 + j) * DIMV + c] *= sNorm[r0 + j];
    }

    // ---- stage 5: wait E_bond; f32x2 channel-pair pass -> bil & wm partials ----
    asm volatile("cp.async.wait_group 0;\n" ::: "memory");
    __syncthreads();
    {
        const int cp = tid & 63;    // channels 2cp, 2cp+1
        const int h  = tid >> 6;    // 0..7 -> rows 2h, 2h+1
        float e0lo = E_bond[2 * cp], e0hi = E_bond[2 * cp + 1];
        float bslo = (float)(NTOT - NA) * e0lo * e0lo;
        float bshi = (float)(NTOT - NA) * e0hi * e0hi;
        ull bil2 = 0ULL, wm2 = 0ULL;
        #pragma unroll
        for (int jj = 0; jj < 2; jj++) {
            int a = 2 * h + jj;
            ull s2; PACK2(s2, bslo, bshi);
            ull pa2 = 0ULL;
            unsigned eaddr = sE_b + (unsigned)(a * NA * DIMV + 2 * cp) * 4u;
            unsigned maddr = sM_b + (unsigned)(2 * cp) * 4u;
            #pragma unroll
            for (int b = 0; b < NA; b++) {
                ull e2, m2;
                LDS_U64(e2, eaddr + b * DIMV * 4);
                LDS_U64(m2, maddr + b * DIMV * 4);
                FMA2(s2, e2, e2);
                FMA2(pa2, m2, e2);
            }
            float slo, shi;
            UNPACK2(slo, shi, s2);
            float invlo = 1.0f / fmaxf(sqrtf(slo), EPSV);
            float invhi = 1.0f / fmaxf(sqrtf(shi), EPSV);
            float mlo = sM[a * DIMV + 2 * cp], mhi = sM[a * DIMV + 2 * cp + 1];
            ull wa2; PACK2(wa2, mlo * invlo, mhi * invhi);
            FMA2(bil2, wa2, pa2);
            ADD2(wm2, wa2);
        }
        unsigned baddr = (unsigned)__cvta_generic_to_shared(sRedB + h * DIMV + 2 * cp);
        unsigned waddr = (unsigned)__cvta_generic_to_shared(sRedW + h * DIMV + 2 * cp);
        STS_U64(baddr, bil2);
        STS_U64(waddr, wm2);
    }
    __syncthreads();

    // ---- stage 6: final per-molecule reductions (8-way); publish Wm ----
    float wmv = 0.f;   // valid for g==0 threads (reused in phase B)
    if (g == 0) {
        float bil = 0.f;
        #pragma unroll
        for (int h = 0; h < 8; h++) bil += sRedB[h * DIMV + c];
        #pragma unroll
        for (int h = 0; h < 8; h++) wmv += sRedW[h * DIMV + c];
        float mm = 0.f;
        #pragma unroll
        for (int a = 0; a < NA; a++) mm += sM[a * DIMV + c];
        bilArr[c] = bil;
        mmArr[c]  = mm;
        g_Wm[m * DIMV + c] = wmv;
        __threadfence();
    }
    __syncthreads();

    // ---- grid barrier (ticket-based, monotonic counter, replay-safe) ----
    if (tid == 0) {
        int t = atomicAdd(&g_ctr, 1);
        int target = ((t >> 6) + 1) << 6;
        while (*(volatile int*)&g_ctr < target) __nanosleep(64);
        __threadfence();
    }
    __syncthreads();

    // ---- phase B: S, tn, 2-layer MLP, projection ----
    {
        float sp = 0.f;
        #pragma unroll
        for (int j = 0; j < 16; j++)
            sp += g_Wm[(g * 16 + j) * DIMV + c];
        sPart[g * DIMV + c] = sp;
    }
    __syncthreads();
    if (g == 0) {
        float S = sPart[c] + sPart[DIMV + c] + sPart[2 * DIMV + c] + sPart[3 * DIMV + c];
        sx[c] = bilArr[c] + e0c * (S - wmv) * mmArr[c];
    }
    __syncthreads();

    // layer 0 (weights straight from global; independent load batch)
    {
        const float4* x4 = (const float4*)(sx + g * 32);
        float a = 0.f, b = 0.f;
        #pragma unroll
        for (int jv = 0; jv < 8; jv++) {
            float4 xv = x4[jv];
            int k = g * 32 + jv * 4;
            a += xv.x * W0[(k + 0) * DIMV + c];
            b += xv.y * W0[(k + 1) * DIMV + c];
            a += xv.z * W0[(k + 2) * DIMV + c];
            b += xv.w * W0[(k + 3) * DIMV + c];
        }
        sPart[g * DIMV + c] = a + b;
    }
    __syncthreads();
    if (g == 0)
        sy[c] = fmaxf(sPart[c] + sPart[DIMV + c] + sPart[2 * DIMV + c] + sPart[3 * DIMV + c] + b0[c], 0.f);
    __syncthreads();

    // layer 1
    {
        const float4* y4 = (const float4*)(sy + g * 32);
        float a = 0.f, b = 0.f;
        #pragma unroll
        for (int jv = 0; jv < 8; jv++) {
            float4 yv = y4[jv];
            int k = g * 32 + jv * 4;
            a += yv.x * W1[(k + 0) * DIMV + c];
            b += yv.y * W1[(k + 1) * DIMV + c];
            a += yv.z * W1[(k + 2) * DIMV + c];
            b += yv.w * W1[(k + 3) * DIMV + c];
        }
        sPart[g * DIMV + c] = a + b;
    }
    __syncthreads();

    if (g == 0) {
        float a1 = fmaxf(sPart[c] + sPart[DIMV + c] + sPart[2 * DIMV + c] + sPart[3 * DIMV + c] + b1[c], 0.f);
        float r = a1 * Wp[c];
        #pragma unroll
        for (int o = 16; o > 0; o >>= 1) r += __shfl_xor_sync(0xffffffffu, r, o);
        if ((c & 31) == 0) sr[c >> 5] = r;
    }
    __syncthreads();
    if (tid == 0) out[m] = sr[0] + sr[1] + sr[2] + sr[3] + bp[0];
}

extern "C" void kernel_launch(void* const* d_in, const int* in_sizes, int n_in,
                              void* d_out, int out_size) {
    const int*   fp     = (const int*)d_in[0];
    const float* adj    = (const float*)d_in[1];
    const int*   bidx   = (const int*)d_in[2];
    const float* E_fp   = (const float*)d_in[3];
    const float* E_bond = (const float*)d_in[4];
    const float* W_fp   = (const float*)d_in[5];
    const float* b_fp   = (const float*)d_in[6];
    const float* W0     = (const float*)d_in[7];
    const float* b0     = (const float*)d_in[8];
    const float* W1     = (const float*)d_in[9];
    const float* b1     = (const float*)d_in[10];
    const float* Wp     = (const float*)d_in[11];
    const float* bp     = (const float*)d_in[12];
    float* out = (float*)d_out;

    size_t smem_bytes = SMEM_FLOATS * sizeof(float);
    cudaFuncSetAttribute(k_fused, cudaFuncAttributeMaxDynamicSharedMemorySize,
                         (int)smem_bytes);
    k_fused<<<NMOL, 512, smem_bytes>>>(fp, adj, bidx, E_fp, E_bond, W_fp, b_fp,
                                       W0, b0, W1, b1, Wp, bp, out);
}